// round 13
// baseline (speedup 1.0000x reference)
#include <cuda_runtime.h>

// BiRealConv2d: y = conv3x3(sign(x), scale_o * sign(w)), pad 1, stride 1.
// Weights here are uniform[0,1)*1e-3 (non-negative) -> sign(w)=+1 a.s., so
// y[n,o,h,w] = scale_o * boxsum3x3(sum_c sign(x))[n,h,w].
// Blocks 32..159 record any weight with sign != +1 at deterministic slots;
// phase 3 patches those contributions inline -> exact for arbitrary data.
//
// ONE kernel, grid = 444 = 3 x 148 SMs (uniform CTA distribution: no 4th-CTA
// straggler SMs). Tiles are GLOBAL-row ranges over the flattened (n,h) axis:
// blocks 0..31 own 9 rows, 32..443 own 8 rows. Tiles may cross image
// boundaries; every T row is keyed by its own (image, local row) and the
// box-sum zero-pads at each image's top/bottom edge, so results are exact.
// Per block: channel-sum T (+1 halo row each side) into smem in ONE balanced
// round (<=308 tasks over 320 threads), per-thread 3x3 box-sum in registers,
// broadcast-store all 128 output channels. Weight scales are produced before
// tile work and consumed behind a monotonic counter (graph-replay safe; all
// 444 blocks co-resident -> spin cannot deadlock; wait is ~zero in practice).

#define N_    32
#define C_    128
#define H_    112
#define W_    112
#define HW_   (H_ * W_)       // 12544
#define P4_   (HW_ / 4)       // 3136
#define W4_   (W_ / 4)        // 28
#define OC_   128
#define WPO_  (C_ * 9)        // 1152
#define WPO4_ (WPO_ / 4)      // 288

#define GR_   (N_ * H_)       // 3584 global rows
#define NB_   444             // 3 * 148
#define TPB   320             // 10 warps
#define MAXR  9               // max rows per tile

__device__ float g_scale[OC_];
__device__ int   g_na[OC_];
__device__ signed char g_acode[OC_ * WPO_];   // 0 normal, -1 zero, -2 negative
__device__ unsigned long long g_epoch;        // monotonic across launches
__device__ unsigned long long g_wdone;        // +=OC_ per launch

__device__ __forceinline__ float sgnf(float v) {
    return (float)((v > 0.f) - (v < 0.f));
}

__global__ void __launch_bounds__(TPB, 3)
fused(const float* __restrict__ x, const float* __restrict__ w,
      float* __restrict__ y) {
    const int t   = threadIdx.x;
    const int bid = blockIdx.x;
    const int r0  = (bid < 32) ? 9 * bid : 8 * bid + 32;   // first global row
    const int nr  = (bid < 32) ? 9 : 8;                    // rows in this tile

    __shared__ float Ts[(MAXR + 2) * W_];   // T rows r0-1 .. r0+nr (global)
    __shared__ float s_scale[OC_];
    __shared__ int   s_na[OC_];
    __shared__ float red[TPB];
    __shared__ unsigned long long se;

    if (t == 0) se = atomicAdd(&g_epoch, 1ULL) / NB_ + 1ULL;
    __syncthreads();
    const unsigned long long e = se;

    // ---- producer duty: blocks 32..159 emit scale/anomaly data for channel o
    if (bid >= 32 && bid < 32 + OC_) {
        const int o = bid - 32;
        float s = 0.f;
        int   na = 0;
        if (t < WPO4_) {
            float4 v = reinterpret_cast<const float4*>(w + o * WPO_)[t];
            const float vv[4] = {v.x, v.y, v.z, v.w};
#pragma unroll
            for (int q = 0; q < 4; ++q) {
                s += fabsf(vv[q]);
                signed char code = 0;
                if (vv[q] <= 0.f) { code = (vv[q] < 0.f) ? -2 : -1; na = 1; }
                g_acode[o * WPO_ + t * 4 + q] = code;
            }
        }
        red[t] = s;
        int any = __syncthreads_or(na);
        // deterministic tree reduce over 320 = 64*5
        if (t < 160) red[t] += red[t + 160];
        __syncthreads();
        if (t < 80)  red[t] += red[t + 80];
        __syncthreads();
        if (t < 40)  red[t] += red[t + 40];
        __syncthreads();
        if (t < 20)  red[t] += red[t + 20];
        __syncthreads();
        if (t < 10)  red[t] += red[t + 10];
        __syncthreads();
        if (t == 0) {
            float tot = 0.f;
#pragma unroll
            for (int q = 0; q < 10; ++q) tot += red[q];
            g_scale[o] = tot / (float)WPO_;
            g_na[o]    = any;
            __threadfence();
            atomicAdd(&g_wdone, 1ULL);
        }
        __syncthreads();
    }

    // ---- phase 1: channel-sum for global rows r0-1 .. r0+nr (one round)
    const int TTn = (nr + 2) * W4_;          // <= 308
    if (t < TTn) {
        int row = t / W4_;                   // 0 .. nr+1
        int c4  = t - row * W4_;
        int gr  = r0 - 1 + row;              // global row
        float4 acc = make_float4(0.f, 0.f, 0.f, 0.f);
        if ((unsigned)gr < (unsigned)GR_) {
            int n  = gr / H_;
            int lr = gr - n * H_;
            const float4* p = reinterpret_cast<const float4*>(x)
                            + (size_t)n * (C_ * P4_) + lr * W4_ + c4;
#pragma unroll 8
            for (int c = 0; c < C_; ++c) {
                float4 v = p[(size_t)c * P4_];
                acc.x += sgnf(v.x); acc.y += sgnf(v.y);
                acc.z += sgnf(v.z); acc.w += sgnf(v.w);
            }
        }
        reinterpret_cast<float4*>(Ts)[t] = acc;
    }
    __syncthreads();

    // ---- weights ready? (zero wait in practice). Stage scales in smem.
    if (t == 0) {
        while (atomicAdd(&g_wdone, 0ULL) < (unsigned long long)OC_ * e)
            __nanosleep(64);
    }
    __syncthreads();
    if (t < OC_) { s_scale[t] = g_scale[t]; s_na[t] = g_na[t]; }
    __syncthreads();

    // ---- phase 2+3: per-thread box-sum (registers), then broadcast-store.
    // Vertical zero-padding applied at IMAGE edges (lh==0 / lh==111), which
    // also handles tiles that cross image boundaries exactly.
    if (t < nr * W4_) {
        const int rj = t / W4_;
        const int c4 = t - rj * W4_;
        const int g  = r0 + rj;              // global output row
        const int n  = g / H_;
        const int lh = g - n * H_;           // local row in image n

        float4 acc = make_float4(0.f, 0.f, 0.f, 0.f);
        // mid row (always), top iff lh>0, bottom iff lh<H-1
        {
            const float* row = Ts + (rj + 1) * W_;
            float4 c = reinterpret_cast<const float4*>(row)[c4];
            float  l  = (c4 > 0)        ? row[c4 * 4 - 1] : 0.f;
            float  rg = (c4 < W4_ - 1)  ? row[c4 * 4 + 4] : 0.f;
            acc.x += l   + c.x + c.y;
            acc.y += c.x + c.y + c.z;
            acc.z += c.y + c.z + c.w;
            acc.w += c.z + c.w + rg;
        }
        if (lh > 0) {
            const float* row = Ts + rj * W_;
            float4 c = reinterpret_cast<const float4*>(row)[c4];
            float  l  = (c4 > 0)        ? row[c4 * 4 - 1] : 0.f;
            float  rg = (c4 < W4_ - 1)  ? row[c4 * 4 + 4] : 0.f;
            acc.x += l   + c.x + c.y;
            acc.y += c.x + c.y + c.z;
            acc.z += c.y + c.z + c.w;
            acc.w += c.z + c.w + rg;
        }
        if (lh < H_ - 1) {
            const float* row = Ts + (rj + 2) * W_;
            float4 c = reinterpret_cast<const float4*>(row)[c4];
            float  l  = (c4 > 0)        ? row[c4 * 4 - 1] : 0.f;
            float  rg = (c4 < W4_ - 1)  ? row[c4 * 4 + 4] : 0.f;
            acc.x += l   + c.x + c.y;
            acc.y += c.x + c.y + c.z;
            acc.z += c.y + c.z + c.w;
            acc.w += c.z + c.w + rg;
        }

        float4* y4 = reinterpret_cast<float4*>(y)
                   + (size_t)n * (OC_ * P4_) + lh * W4_ + c4;
#pragma unroll 4
        for (int o = 0; o < OC_; ++o) {
            float sc = s_scale[o];
            float4 val = make_float4(sc * acc.x, sc * acc.y,
                                     sc * acc.z, sc * acc.w);
            if (s_na[o] != 0) {
                // exact sparse correction: scale * (sign(w)-1) * sign(x)
                for (int f = 0; f < WPO_; ++f) {
                    int code = (int)g_acode[o * WPO_ + f];
                    if (code == 0) continue;
                    int c  = f / 9, kk = f % 9;
                    int dh = kk / 3 - 1, dw = kk % 3 - 1;
                    int hh = lh + dh;
                    if ((unsigned)hh >= (unsigned)H_) continue;
                    const float* xr = x + ((size_t)n * C_ + c) * HW_ + hh * W_;
#pragma unroll
                    for (int q = 0; q < 4; ++q) {
                        int ww = c4 * 4 + q + dw;
                        if ((unsigned)ww >= (unsigned)W_) continue;
                        float add = sc * (float)code * sgnf(xr[ww]);
                        if (q == 0) val.x += add;
                        else if (q == 1) val.y += add;
                        else if (q == 2) val.z += add;
                        else val.w += add;
                    }
                }
            }
            __stcs(y4 + (size_t)o * P4_, val);
        }
    }
}

extern "C" void kernel_launch(void* const* d_in, const int* in_sizes, int n_in,
                              void* d_out, int out_size) {
    const float* x = (const float*)d_in[0];
    const float* w = (const float*)d_in[1];
    float* y = (float*)d_out;
    fused<<<NB_, TPB>>>(x, w, y);
}